// round 7
// baseline (speedup 1.0000x reference)
#include <cuda_runtime.h>
#include <cuda_fp16.h>
#include <cstdint>

// COO SpMM: out[src[e], :] += att[e] * X[dst[e], :], D = 128 fp32.
//
// Packed CSR via counting sort + fp16 gather. 4 kernels:
//   1. prep_hist: X fp32->fp16 convert + src histogram (counters are a
//      maintained zero-invariant: spmm resets them; statics start zero)
//   2. scan: single-kernel decoupled-lookback exclusive scan -> rowptr+cursor
//   3. scatter: packed 4B meta (dst<<15 | att*32767), sorted by src;
//      also resets the scan lookback flags for the next graph replay
//   4. spmm: warp-per-node gather-FMA fp16->fp32, streaming store
//
// Footprint: X_half 25.6MB + meta 12.8MB + ptrs ~1.2MB = ~40MB << 126MB L2.

#define SCAN_BLK 1024
#define N_MAX 131072
#define E_MAX 3276800
#define NSB_MAX (N_MAX / SCAN_BLK)

__device__ int    g_count[N_MAX];      // histogram; zero invariant across calls
__device__ int    g_cursor[N_MAX];     // scatter fill cursor
__device__ int    g_rowptr[N_MAX + 1];
__device__ volatile int g_bflag[NSB_MAX];  // 0=none 1=agg 2=prefix; reset by scatter
__device__ volatile int g_bagg[NSB_MAX];
__device__ volatile int g_bpre[NSB_MAX];
__device__ unsigned g_edge[E_MAX];                  // dst<<15 | att15
__device__ uint2    g_xh[(size_t)N_MAX * 32];       // X fp16: 32 uint2/row

__device__ __forceinline__ bool detect64(const void* edges) {
    const int* w = (const int*)edges;
    return (w[1] == 0 && w[3] == 0 && w[5] == 0);   // ids << 2^31
}

__device__ __forceinline__ unsigned h2_bits(__half2 h) {
    return *reinterpret_cast<unsigned*>(&h);
}

// Fused: convert X -> fp16 (DRAM-stream bound) + histogram src (atomic bound).
__global__ void prep_hist_kernel(const float4* __restrict__ X, int N,
                                 const void* __restrict__ edges, int E) {
    int stride = gridDim.x * blockDim.x;
    int tid = blockIdx.x * blockDim.x + threadIdx.x;

    int n4 = N * 32;
    for (int i = tid; i < n4; i += stride) {
        float4 v = __ldcs(X + i);
        g_xh[i] = make_uint2(h2_bits(__floats2half2_rn(v.x, v.y)),
                             h2_bits(__floats2half2_rn(v.z, v.w)));
    }

    const bool is64 = detect64(edges);
    if (is64) {
        const long long* s = (const long long*)edges;
        for (int e = tid; e < E; e += stride)
            atomicAdd(&g_count[(int)s[e]], 1);
    } else {
        const int* s = (const int*)edges;
        for (int e = tid; e < E; e += stride)
            atomicAdd(&g_count[s[e]], 1);
    }
}

// Single-kernel exclusive scan, decoupled lookback. grid = npad/1024 (<=128
// blocks, all resident in wave 1 -> spin-free-of-deadlock). Requires
// g_bflag[] == 0 at entry (scatter resets it after use).
__global__ void __launch_bounds__(SCAN_BLK) scan_kernel() {
    __shared__ int wsum[32];
    __shared__ int s_prefix;
    int lane = threadIdx.x & 31;
    int warp = threadIdx.x >> 5;
    int i = blockIdx.x * SCAN_BLK + threadIdx.x;

    int v = g_count[i];
    // warp inclusive scan
    int x = v;
    #pragma unroll
    for (int off = 1; off < 32; off <<= 1) {
        int t = __shfl_up_sync(0xFFFFFFFFu, x, off);
        if (lane >= off) x += t;
    }
    if (lane == 31) wsum[warp] = x;
    __syncthreads();
    if (warp == 0) {
        int y = wsum[lane];
        #pragma unroll
        for (int off = 1; off < 32; off <<= 1) {
            int t = __shfl_up_sync(0xFFFFFFFFu, y, off);
            if (lane >= off) y += t;
        }
        wsum[lane] = y;
    }
    __syncthreads();
    int block_excl = (warp > 0) ? wsum[warp - 1] : 0;
    int incl = block_excl + x;
    int total = wsum[31];

    // decoupled lookback (thread 0)
    if (threadIdx.x == 0) {
        int bid = blockIdx.x;
        if (bid == 0) {
            g_bpre[0] = total;
            __threadfence();
            g_bflag[0] = 2;
            s_prefix = 0;
        } else {
            g_bagg[bid] = total;
            __threadfence();
            g_bflag[bid] = 1;
            int run = 0, j = bid - 1;
            while (true) {
                int f;
                do { f = g_bflag[j]; } while (f == 0);
                if (f == 2) { run += g_bpre[j]; break; }
                run += g_bagg[j];
                j--;
            }
            g_bpre[bid] = run + total;
            __threadfence();
            g_bflag[bid] = 2;
            s_prefix = run;
        }
    }
    __syncthreads();
    int r = s_prefix + incl - v;        // global exclusive
    g_rowptr[i] = r;
    g_cursor[i] = r;
}

// Packed scatter: meta = dst << 15 | round(att * 32767). att in [0,1) so the
// 15-bit quantization adds ~3e-5 relative error (negligible vs fp16 gather).
__global__ void scatter_kernel(const void* __restrict__ edges,
                               const float* __restrict__ att, int E) {
    // reset lookback flags for next graph replay (scan already done)
    if (blockIdx.x == 0 && threadIdx.x < NSB_MAX) g_bflag[threadIdx.x] = 0;

    const bool is64 = detect64(edges);
    int half = E >> 1;
    int stride = gridDim.x * blockDim.x;
    for (int i = blockIdx.x * blockDim.x + threadIdx.x; i < half; i += stride) {
        int s0, s1, d0, d1;
        if (is64) {
            longlong2 s = __ldcs((const longlong2*)edges + i);
            longlong2 d = __ldcs((const longlong2*)((const long long*)edges + E) + i);
            s0 = (int)s.x; s1 = (int)s.y; d0 = (int)d.x; d1 = (int)d.y;
        } else {
            int2 s = __ldcs((const int2*)edges + i);
            int2 d = __ldcs((const int2*)((const int*)edges + E) + i);
            s0 = s.x; s1 = s.y; d0 = d.x; d1 = d.y;
        }
        float2 a = __ldcs((const float2*)att + i);
        unsigned q0 = min(__float2int_rn(a.x * 32767.f), 32767);
        unsigned q1 = min(__float2int_rn(a.y * 32767.f), 32767);
        int p0 = atomicAdd(&g_cursor[s0], 1);
        g_edge[p0] = ((unsigned)d0 << 15) | q0;
        int p1 = atomicAdd(&g_cursor[s1], 1);
        g_edge[p1] = ((unsigned)d1 << 15) | q1;
    }
    if (blockIdx.x == 0 && threadIdx.x == 0 && (E & 1)) {
        int e = E - 1;
        int s, d;
        if (is64) {
            s = (int)((const long long*)edges)[e];
            d = (int)((const long long*)edges)[(long long)E + e];
        } else {
            s = ((const int*)edges)[e];
            d = ((const int*)edges)[(long long)E + e];
        }
        unsigned q = min(__float2int_rn(att[e] * 32767.f), 32767);
        int p = atomicAdd(&g_cursor[s], 1);
        g_edge[p] = ((unsigned)d << 15) | q;
    }
}

__device__ __forceinline__ void meta_fma(unsigned u, uint2 h, int lane, float4& acc) {
    float a = (float)(int)(u & 0x7FFFu) * (1.f / 32767.f);
    int dst_unused = 0; (void)dst_unused; (void)lane;
    float2 lo = __half22float2(*(__half2*)&h.x);
    float2 hi = __half22float2(*(__half2*)&h.y);
    acc.x = fmaf(a, lo.x, acc.x); acc.y = fmaf(a, lo.y, acc.y);
    acc.z = fmaf(a, hi.x, acc.z); acc.w = fmaf(a, hi.y, acc.w);
}

// Warp per node: lane l owns feature quad l. fp16 gather (8B/lane = 256B/row
// coalesced), fp32 accumulate, streaming store. 8 independent gathers in
// flight. Resets g_count to keep the zero-invariant for the next replay.
__global__ void __launch_bounds__(256) spmm_kernel(float4* __restrict__ out, int N) {
    int lane = threadIdx.x & 31;
    int node = (blockIdx.x * blockDim.x + threadIdx.x) >> 5;
    if (node >= N) return;

    int e = __ldg(&g_rowptr[node]);
    int end = __ldg(&g_rowptr[node + 1]);
    if (lane == 0) g_count[node] = 0;       // restore zero-invariant

    float4 acc = make_float4(0.f, 0.f, 0.f, 0.f);

    for (; e + 8 <= end; e += 8) {
        unsigned m[8]; uint2 h[8];
        #pragma unroll
        for (int k = 0; k < 8; k++) m[k] = __ldcs(&g_edge[e + k]);
        #pragma unroll
        for (int k = 0; k < 8; k++) h[k] = __ldg(&g_xh[(size_t)(m[k] >> 15) * 32 + lane]);
        #pragma unroll
        for (int k = 0; k < 8; k++) meta_fma(m[k], h[k], lane, acc);
    }
    for (; e + 2 <= end; e += 2) {
        unsigned m0 = __ldcs(&g_edge[e]);
        unsigned m1 = __ldcs(&g_edge[e + 1]);
        uint2 h0 = __ldg(&g_xh[(size_t)(m0 >> 15) * 32 + lane]);
        uint2 h1 = __ldg(&g_xh[(size_t)(m1 >> 15) * 32 + lane]);
        meta_fma(m0, h0, lane, acc);
        meta_fma(m1, h1, lane, acc);
    }
    if (e < end) {
        unsigned m = __ldcs(&g_edge[e]);
        uint2 h = __ldg(&g_xh[(size_t)(m >> 15) * 32 + lane]);
        meta_fma(m, h, lane, acc);
    }

    __stcs(out + (size_t)node * 32 + lane, acc);
}

extern "C" void kernel_launch(void* const* d_in, const int* in_sizes, int n_in,
                              void* d_out, int out_size) {
    const void* edges = d_in[0];               // (2, E) int32 or int64
    const float* att = (const float*)d_in[1];  // (E,)
    const float4* X = (const float4*)d_in[3];  // (N, 128) fp32
    float4* out = (float4*)d_out;

    int E = in_sizes[1];
    int N = out_size / 128;
    int npad = ((N + 1 + SCAN_BLK - 1) / SCAN_BLK) * SCAN_BLK;
    int nsb = npad / SCAN_BLK;                 // <= 128 blocks, single wave

    prep_hist_kernel<<<2048, 256>>>(X, N, edges, E);
    scan_kernel<<<nsb, SCAN_BLK>>>();
    scatter_kernel<<<2048, 256>>>(edges, att, E);
    spmm_kernel<<<(N + 7) / 8, 256>>>(out, N);
}